// round 2
// baseline (speedup 1.0000x reference)
#include <cuda_runtime.h>

// LSTM B=4096,T=512,F=32,H=60. Persistent CTA owns 28 batch rows, all 512 steps.
// Key: fma.rn.f32x2 packed FMAs (2x fp32 pipe rate vs 3-reg FFMA).
// Weights gate-interleaved (i,j,f,o) per hidden unit -> packed (wi,wj),(wf,wo).
// Activations stored DUPLICATED (a,a) in smem so packed operands need no PACK.

#define T_STEPS 512
#define F_IN    32
#define H_DIM   60
#define K_DIM   92
#define NCOL    240        // 4*H
#define BB      28         // batch rows per CTA
#define RPT     7          // rows per thread (BB/4)
#define THREADS 256
#define FORGET_BIAS 1.0f

#define ASTRIDE (K_DIM * 2 + 8)   // floats per dup-A row: 92 pairs + pad = 192
// smem layout (floats): W[92*240] | Adup[28*192] | bias[240]
#define W_ELEMS   (K_DIM * NCOL)            // 22080
#define A_ELEMS   (BB * ASTRIDE)            // 5376
#define SMEM_FLOATS (W_ELEMS + A_ELEMS + NCOL)
#define SMEM_BYTES  (SMEM_FLOATS * 4)       // ~111 KB

typedef unsigned long long ull;

__device__ __forceinline__ void ffma2(ull& d, ull a, ull b) {
    asm("fma.rn.f32x2 %0, %1, %2, %0;" : "+l"(d) : "l"(a), "l"(b));
}
__device__ __forceinline__ void unpack2(float& lo, float& hi, ull v) {
    asm("mov.b64 {%0, %1}, %2;" : "=f"(lo), "=f"(hi) : "l"(v));
}

__device__ __forceinline__ float sigmoid_f(float x) {
    return __fdividef(1.0f, 1.0f + __expf(-x));
}
__device__ __forceinline__ float tanh_f(float x) {
    float e = __expf(-2.0f * fabsf(x));
    float r = __fdividef(1.0f - e, 1.0f + e);
    return copysignf(r, x);
}

__global__ void __launch_bounds__(THREADS, 1)
lstm_persistent_kernel(const float* __restrict__ x,
                       const float* __restrict__ kernel,   // [92][240] gates i,j,f,o
                       const float* __restrict__ bias,     // [240]
                       const float* __restrict__ dense_w,  // [60]
                       const float* __restrict__ dense_b,  // [1]
                       float* __restrict__ out,
                       int Btotal)
{
    extern __shared__ float smem[];
    float* Wsm  = smem;                        // [k][hcol*4+g]
    float* Asm  = smem + W_ELEMS;              // dup pairs: [row][k] -> (a,a)
    float* bsm  = smem + W_ELEMS + A_ELEMS;    // [hcol*4+g]

    const int tx   = threadIdx.x;
    const int row0 = blockIdx.x * BB;

    // ---- gate-interleave weights: kernel[k][g*60+h] -> Wsm[k*240 + h*4 + g]
    for (int idx = tx; idx < W_ELEMS; idx += THREADS) {
        int k = idx / NCOL, c = idx % NCOL;
        Wsm[idx] = kernel[k * NCOL + (c & 3) * H_DIM + (c >> 2)];
    }
    for (int idx = tx; idx < NCOL; idx += THREADS)
        bsm[idx] = bias[(idx & 3) * H_DIM + (idx >> 2)];
    for (int idx = tx; idx < A_ELEMS; idx += THREADS) Asm[idx] = 0.0f;
    __syncthreads();

    // ---- thread map: rgroup 0..3 owns 7 rows; hcol 0..63 (active < 60)
    const int rg   = tx >> 6;
    const int hcol = tx & 63;
    const bool active = (hcol < H_DIM);

    ull bij = 0ull, bfo = 0ull;
    if (active) {
        ulonglong2 bv = *(const ulonglong2*)&bsm[hcol * 4];
        bij = bv.x; bfo = bv.y;
    }

    float c_state[RPT];
#pragma unroll
    for (int r = 0; r < RPT; r++) c_state[r] = 0.0f;

    // ---- x tile prefetch: 28*32 = 896 elems; threads own up to 4
    const float* xp[4];
    int sidx[4];
    bool xv[4];
#pragma unroll
    for (int i = 0; i < 4; i++) {
        int idx = tx + i * THREADS;
        int r = idx >> 5, f = idx & 31;
        xv[i]  = (idx < BB * F_IN) && (row0 + r) < Btotal;
        xp[i]  = xv[i] ? (x + (size_t)(row0 + r) * (T_STEPS * F_IN) + f) : x;
        sidx[i] = r * ASTRIDE + f * 2;
    }
    float xr[4];
#pragma unroll
    for (int i = 0; i < 4; i++) xr[i] = xv[i] ? xp[i][0] : 0.0f;

    const ulonglong2* Wp = (const ulonglong2*)Wsm;              // [k*60 + hcol]
    const ulonglong2* Ap = (const ulonglong2*)(Asm + rg * RPT * ASTRIDE);
    const int arow = ASTRIDE / 4;                               // ull2 per A row = 48

    float hnew[RPT];

    for (int t = 0; t < T_STEPS; ++t) {
        // store duplicated x_t  (disjoint from h region)
#pragma unroll
        for (int i = 0; i < 4; i++)
            if (xv[i]) *(float2*)&Asm[sidx[i]] = make_float2(xr[i], xr[i]);
        __syncthreads();

        // prefetch next x (overlaps GEMM)
        if (t < T_STEPS - 1) {
#pragma unroll
            for (int i = 0; i < 4; i++)
                if (xv[i]) xr[i] = xp[i][(t + 1) * F_IN];
        }

        if (active) {
            ull acc_ij[RPT], acc_fo[RPT];
#pragma unroll
            for (int r = 0; r < RPT; r++) { acc_ij[r] = bij; acc_fo[r] = bfo; }

#pragma unroll 2
            for (int k2 = 0; k2 < K_DIM / 2; k2++) {
                ulonglong2 w0 = Wp[(2 * k2)     * H_DIM + hcol]; // (wi,wj),(wf,wo)
                ulonglong2 w1 = Wp[(2 * k2 + 1) * H_DIM + hcol];
#pragma unroll
                for (int r = 0; r < RPT; r++) {
                    ulonglong2 aa = Ap[r * arow + k2];           // (a_k,a_k),(a_k1,a_k1)
                    ffma2(acc_ij[r], aa.x, w0.x);
                    ffma2(acc_fo[r], aa.x, w0.y);
                    ffma2(acc_ij[r], aa.y, w1.x);
                    ffma2(acc_fo[r], aa.y, w1.y);
                }
            }

#pragma unroll
            for (int r = 0; r < RPT; r++) {
                float gi, gj, gf, go;
                unpack2(gi, gj, acc_ij[r]);
                unpack2(gf, go, acc_fo[r]);
                float ig = sigmoid_f(gi);
                float jg = tanh_f(gj);
                float fg = sigmoid_f(gf + FORGET_BIAS);
                float og = sigmoid_f(go);
                float c2 = c_state[r] * fg + ig * jg;
                c_state[r] = c2;
                hnew[r] = tanh_f(c2) * og;
            }
        }
        __syncthreads();   // all GEMM reads done before h overwrite

        if (active) {
#pragma unroll
            for (int r = 0; r < RPT; r++)
                *(float2*)&Asm[(rg * RPT + r) * ASTRIDE + (F_IN + hcol) * 2]
                    = make_float2(hnew[r], hnew[r]);
        }
    }
    __syncthreads();

    // final dense
    if (tx < BB && (row0 + tx) < Btotal) {
        float s = dense_b[0];
#pragma unroll
        for (int k = 0; k < H_DIM; k++)
            s = fmaf(Asm[tx * ASTRIDE + (F_IN + k) * 2], dense_w[k], s);
        out[row0 + tx] = s;
    }
}

extern "C" void kernel_launch(void* const* d_in, const int* in_sizes, int n_in,
                              void* d_out, int out_size)
{
    const float* x       = (const float*)d_in[0];
    const float* kernel  = (const float*)d_in[1];
    const float* bias    = (const float*)d_in[2];
    const float* dense_w = (const float*)d_in[3];
    const float* dense_b = (const float*)d_in[4];
    float* out = (float*)d_out;

    int Btotal = in_sizes[0] / (T_STEPS * F_IN);      // 4096
    int grid   = (Btotal + BB - 1) / BB;              // 147

    cudaFuncSetAttribute(lstm_persistent_kernel,
                         cudaFuncAttributeMaxDynamicSharedMemorySize, SMEM_BYTES);

    lstm_persistent_kernel<<<grid, THREADS, SMEM_BYTES>>>(
        x, kernel, bias, dense_w, dense_b, out, Btotal);
}

// round 3
// speedup vs baseline: 1.0039x; 1.0039x over previous
#include <cuda_runtime.h>

// LSTM B=4096,T=512,F=32,H=60. Persistent CTA owns 28 batch rows, all 512 steps.
// Key: fma.rn.f32x2 packed FMAs (2x fp32 pipe rate vs 3-reg FFMA).
// Weights gate-interleaved (i,j,f,o) per hidden unit -> packed (wi,wj),(wf,wo).
// Activations stored DUPLICATED (a,a) in smem so packed operands need no PACK.

#define T_STEPS 512
#define F_IN    32
#define H_DIM   60
#define K_DIM   92
#define NCOL    240        // 4*H
#define BB      28         // batch rows per CTA
#define RPT     7          // rows per thread (BB/4)
#define THREADS 256
#define FORGET_BIAS 1.0f

#define ASTRIDE (K_DIM * 2 + 8)   // floats per dup-A row: 92 pairs + pad = 192
// smem layout (floats): W[92*240] | Adup[28*192] | bias[240]
#define W_ELEMS   (K_DIM * NCOL)            // 22080
#define A_ELEMS   (BB * ASTRIDE)            // 5376
#define SMEM_FLOATS (W_ELEMS + A_ELEMS + NCOL)
#define SMEM_BYTES  (SMEM_FLOATS * 4)       // ~111 KB

typedef unsigned long long ull;

__device__ __forceinline__ void ffma2(ull& d, ull a, ull b) {
    asm("fma.rn.f32x2 %0, %1, %2, %0;" : "+l"(d) : "l"(a), "l"(b));
}
__device__ __forceinline__ void unpack2(float& lo, float& hi, ull v) {
    asm("mov.b64 {%0, %1}, %2;" : "=f"(lo), "=f"(hi) : "l"(v));
}

__device__ __forceinline__ float sigmoid_f(float x) {
    return __fdividef(1.0f, 1.0f + __expf(-x));
}
__device__ __forceinline__ float tanh_f(float x) {
    float e = __expf(-2.0f * fabsf(x));
    float r = __fdividef(1.0f - e, 1.0f + e);
    return copysignf(r, x);
}

__global__ void __launch_bounds__(THREADS, 1)
lstm_persistent_kernel(const float* __restrict__ x,
                       const float* __restrict__ kernel,   // [92][240] gates i,j,f,o
                       const float* __restrict__ bias,     // [240]
                       const float* __restrict__ dense_w,  // [60]
                       const float* __restrict__ dense_b,  // [1]
                       float* __restrict__ out,
                       int Btotal)
{
    extern __shared__ float smem[];
    float* Wsm  = smem;                        // [k][hcol*4+g]
    float* Asm  = smem + W_ELEMS;              // dup pairs: [row][k] -> (a,a)
    float* bsm  = smem + W_ELEMS + A_ELEMS;    // [hcol*4+g]

    const int tx   = threadIdx.x;
    const int row0 = blockIdx.x * BB;

    // ---- gate-interleave weights: kernel[k][g*60+h] -> Wsm[k*240 + h*4 + g]
    for (int idx = tx; idx < W_ELEMS; idx += THREADS) {
        int k = idx / NCOL, c = idx % NCOL;
        Wsm[idx] = kernel[k * NCOL + (c & 3) * H_DIM + (c >> 2)];
    }
    for (int idx = tx; idx < NCOL; idx += THREADS)
        bsm[idx] = bias[(idx & 3) * H_DIM + (idx >> 2)];
    for (int idx = tx; idx < A_ELEMS; idx += THREADS) Asm[idx] = 0.0f;
    __syncthreads();

    // ---- thread map: rgroup 0..3 owns 7 rows; hcol 0..63 (active < 60)
    const int rg   = tx >> 6;
    const int hcol = tx & 63;
    const bool active = (hcol < H_DIM);

    ull bij = 0ull, bfo = 0ull;
    if (active) {
        ulonglong2 bv = *(const ulonglong2*)&bsm[hcol * 4];
        bij = bv.x; bfo = bv.y;
    }

    float c_state[RPT];
#pragma unroll
    for (int r = 0; r < RPT; r++) c_state[r] = 0.0f;

    // ---- x tile prefetch: 28*32 = 896 elems; threads own up to 4
    const float* xp[4];
    int sidx[4];
    bool xv[4];
#pragma unroll
    for (int i = 0; i < 4; i++) {
        int idx = tx + i * THREADS;
        int r = idx >> 5, f = idx & 31;
        xv[i]  = (idx < BB * F_IN) && (row0 + r) < Btotal;
        xp[i]  = xv[i] ? (x + (size_t)(row0 + r) * (T_STEPS * F_IN) + f) : x;
        sidx[i] = r * ASTRIDE + f * 2;
    }
    float xr[4];
#pragma unroll
    for (int i = 0; i < 4; i++) xr[i] = xv[i] ? xp[i][0] : 0.0f;

    const ulonglong2* Wp = (const ulonglong2*)Wsm;              // [k*60 + hcol]
    const ulonglong2* Ap = (const ulonglong2*)(Asm + rg * RPT * ASTRIDE);
    const int arow = ASTRIDE / 4;                               // ull2 per A row = 48

    float hnew[RPT];

    for (int t = 0; t < T_STEPS; ++t) {
        // store duplicated x_t  (disjoint from h region)
#pragma unroll
        for (int i = 0; i < 4; i++)
            if (xv[i]) *(float2*)&Asm[sidx[i]] = make_float2(xr[i], xr[i]);
        __syncthreads();

        // prefetch next x (overlaps GEMM)
        if (t < T_STEPS - 1) {
#pragma unroll
            for (int i = 0; i < 4; i++)
                if (xv[i]) xr[i] = xp[i][(t + 1) * F_IN];
        }

        if (active) {
            ull acc_ij[RPT], acc_fo[RPT];
#pragma unroll
            for (int r = 0; r < RPT; r++) { acc_ij[r] = bij; acc_fo[r] = bfo; }

#pragma unroll 2
            for (int k2 = 0; k2 < K_DIM / 2; k2++) {
                ulonglong2 w0 = Wp[(2 * k2)     * H_DIM + hcol]; // (wi,wj),(wf,wo)
                ulonglong2 w1 = Wp[(2 * k2 + 1) * H_DIM + hcol];
#pragma unroll
                for (int r = 0; r < RPT; r++) {
                    ulonglong2 aa = Ap[r * arow + k2];           // (a_k,a_k),(a_k1,a_k1)
                    ffma2(acc_ij[r], aa.x, w0.x);
                    ffma2(acc_fo[r], aa.x, w0.y);
                    ffma2(acc_ij[r], aa.y, w1.x);
                    ffma2(acc_fo[r], aa.y, w1.y);
                }
            }

#pragma unroll
            for (int r = 0; r < RPT; r++) {
                float gi, gj, gf, go;
                unpack2(gi, gj, acc_ij[r]);
                unpack2(gf, go, acc_fo[r]);
                float ig = sigmoid_f(gi);
                float jg = tanh_f(gj);
                float fg = sigmoid_f(gf + FORGET_BIAS);
                float og = sigmoid_f(go);
                float c2 = c_state[r] * fg + ig * jg;
                c_state[r] = c2;
                hnew[r] = tanh_f(c2) * og;
            }
        }
        __syncthreads();   // all GEMM reads done before h overwrite

        if (active) {
#pragma unroll
            for (int r = 0; r < RPT; r++)
                *(float2*)&Asm[(rg * RPT + r) * ASTRIDE + (F_IN + hcol) * 2]
                    = make_float2(hnew[r], hnew[r]);
        }
    }
    __syncthreads();

    // final dense
    if (tx < BB && (row0 + tx) < Btotal) {
        float s = dense_b[0];
#pragma unroll
        for (int k = 0; k < H_DIM; k++)
            s = fmaf(Asm[tx * ASTRIDE + (F_IN + k) * 2], dense_w[k], s);
        out[row0 + tx] = s;
    }
}

extern "C" void kernel_launch(void* const* d_in, const int* in_sizes, int n_in,
                              void* d_out, int out_size)
{
    const float* x       = (const float*)d_in[0];
    const float* kernel  = (const float*)d_in[1];
    const float* bias    = (const float*)d_in[2];
    const float* dense_w = (const float*)d_in[3];
    const float* dense_b = (const float*)d_in[4];
    float* out = (float*)d_out;

    int Btotal = in_sizes[0] / (T_STEPS * F_IN);      // 4096
    int grid   = (Btotal + BB - 1) / BB;              // 147

    cudaFuncSetAttribute(lstm_persistent_kernel,
                         cudaFuncAttributeMaxDynamicSharedMemorySize, SMEM_BYTES);

    lstm_persistent_kernel<<<grid, THREADS, SMEM_BYTES>>>(
        x, kernel, bias, dense_w, dense_b, out, Btotal);
}

// round 5
// speedup vs baseline: 2.4131x; 2.4038x over previous
#include <cuda_runtime.h>
#include <cuda_bf16.h>
#include <cstdint>

// LSTM B=4096,T=512,F=32,H=60 via mma.sync.m16n8k16 bf16 (3-term hi/lo).
// 128 persistent CTAs x 32 rows. Per step: gates[32x240] = A[32x96]·W^T.
// A cols: 0..31 x_t, 32..91 h, 92 = 1.0 (bias incl. forget), 93..95 zero.
// N gate-interleaved: n = 4u+g, g in {i,j,f,o}; W padded to 256 rows (zeros).
// A double-buffered -> ONE barrier per step. Warp w owns n in [32w, 32w+32).

#define T_STEPS 512
#define F_IN    32
#define H_DIM   60
#define ROWS    32
#define THREADS 256

#define ASTR    104                  // bf16 per A/W row (208 B, conflict-free)
#define ROWB    208
#define ABYTES  (ROWS * ROWB)        // 6656
#define WROWS   256
#define WBYTES  (WROWS * ROWB)       // 53248

#define OFF_AHI 0                    // 2 bufs
#define OFF_ALO (2 * ABYTES)         // 13312 (2 bufs)
#define OFF_WHI (4 * ABYTES)         // 26624
#define OFF_WLO (OFF_WHI + WBYTES)   // 79872
#define OFF_G   (OFF_WLO + WBYTES)   // 133120 : 32 x 64 f32
#define SMEM_BYTES (OFF_G + ROWS * 64 * 4)   // 141312

static __device__ __forceinline__ uint32_t smem_u32(const void* p) {
    uint32_t a;
    asm("{ .reg .u64 t; cvta.to.shared.u64 t, %1; cvt.u32.u64 %0, t; }" : "=r"(a) : "l"(p));
    return a;
}
static __device__ __forceinline__ void ldsm4(uint32_t* r, uint32_t addr) {
    asm volatile("ldmatrix.sync.aligned.m8n8.x4.shared.b16 {%0,%1,%2,%3}, [%4];"
        : "=r"(r[0]), "=r"(r[1]), "=r"(r[2]), "=r"(r[3]) : "r"(addr));
}
static __device__ __forceinline__ void mma16816(float* d, const uint32_t* a, const uint32_t* b) {
    asm volatile("mma.sync.aligned.m16n8k16.row.col.f32.bf16.bf16.f32 "
        "{%0,%1,%2,%3}, {%4,%5,%6,%7}, {%8,%9}, {%0,%1,%2,%3};"
        : "+f"(d[0]), "+f"(d[1]), "+f"(d[2]), "+f"(d[3])
        : "r"(a[0]), "r"(a[1]), "r"(a[2]), "r"(a[3]), "r"(b[0]), "r"(b[1]));
}
static __device__ __forceinline__ float sigmoid_f(float x) {
    return __fdividef(1.0f, 1.0f + __expf(-x));
}
static __device__ __forceinline__ float tanh_f(float x) {
    float e = __expf(-2.0f * fabsf(x));
    float r = __fdividef(1.0f - e, 1.0f + e);
    return copysignf(r, x);
}
static __device__ __forceinline__ uint32_t pack_hi_lo(float v, uint32_t& lo16) {
    __nv_bfloat16 hb = __float2bfloat16_rn(v);
    __nv_bfloat16 lb = __float2bfloat16_rn(v - __bfloat162float(hb));
    lo16 = *(uint16_t*)&lb;
    return *(uint16_t*)&hb;
}

__global__ void __launch_bounds__(THREADS, 1)
lstm_mma_kernel(const float* __restrict__ x,
                const float* __restrict__ kernel,   // [92][240] cols g*60+u
                const float* __restrict__ bias,     // [240]
                const float* __restrict__ dense_w,  // [60]
                const float* __restrict__ dense_b,  // [1]
                float* __restrict__ out, int Btotal)
{
    extern __shared__ char smem[];
    const uint32_t sb = smem_u32(smem);
    const int tid = threadIdx.x, wid = tid >> 5, lane = tid & 31;
    const int row0 = blockIdx.x * ROWS;

    // ---- init: zero A region (both terms, both bufs)
    for (int i = tid; i < OFF_WHI / 4; i += THREADS) ((uint32_t*)smem)[i] = 0u;
    // W hi/lo, gate-interleaved, padded to 256 rows; bias(+forget) at k=92
    for (int idx = tid; idx < WROWS * ASTR; idx += THREADS) {
        int n = idx / ASTR, k = idx - n * ASTR;
        float v = 0.0f;
        if (n < 240) {
            int g = n & 3, u = n >> 2;
            if (k < 92)       v = kernel[k * 240 + g * 60 + u];
            else if (k == 92) v = bias[g * 60 + u] + (g == 2 ? 1.0f : 0.0f);
        }
        __nv_bfloat16 hb = __float2bfloat16_rn(v);
        *(__nv_bfloat16*)(smem + OFF_WHI + n * ROWB + k * 2) = hb;
        *(__nv_bfloat16*)(smem + OFF_WLO + n * ROWB + k * 2) =
            __float2bfloat16_rn(v - __bfloat162float(hb));
    }
    __syncthreads();

    // ones (bias) column k=92 in both A-hi buffers
    if (tid < ROWS) {
        __nv_bfloat16 one = __float2bfloat16_rn(1.0f);
        *(__nv_bfloat16*)(smem + OFF_AHI + tid * ROWB + 92 * 2) = one;
        *(__nv_bfloat16*)(smem + OFF_AHI + ABYTES + tid * ROWB + 92 * 2) = one;
    }

    // ---- x mapping: thread -> (row jr = tid/8, quad q = tid%8)
    const int jr = tid >> 3, q = tid & 7;
    const bool rowOK = (row0 + jr) < Btotal;
    const float4* xp = (const float4*)(x + (size_t)(row0 + jr) * (T_STEPS * F_IN)) + q;
    const int xoff = jr * ROWB + q * 8;

    // store x_0 into buf0
    if (rowOK) {
        float4 v = __ldg(xp);
        uint32_t l0, l1, l2, l3;
        uint32_t h0 = pack_hi_lo(v.x, l0), h1 = pack_hi_lo(v.y, l1);
        uint32_t h2 = pack_hi_lo(v.z, l2), h3 = pack_hi_lo(v.w, l3);
        *(uint2*)(smem + OFF_AHI + xoff) = make_uint2(h0 | (h1 << 16), h2 | (h3 << 16));
        *(uint2*)(smem + OFF_ALO + xoff) = make_uint2(l0 | (l1 << 16), l2 | (l3 << 16));
    }
    __syncthreads();

    // ---- per-lane ldmatrix offsets
    const int aoff = (lane & 15) * ROWB + (lane >> 4) * 16;                 // A frag
    const int boff = ((lane & 7) + ((lane & 16) ? 8 : 0)) * ROWB
                   + ((lane & 8) ? 16 : 0);                                 // B frag
    const int n0 = wid * 32;
    // A bases (buf 0), per term x mf
    uint32_t aHi0 = sb + OFF_AHI + aoff,            aHi1 = aHi0 + 16 * ROWB;
    uint32_t aLo0 = sb + OFF_ALO + aoff,            aLo1 = aLo0 + 16 * ROWB;
    // B bases, per term x pair
    const uint32_t bHi0 = sb + OFF_WHI + n0 * ROWB + boff, bHi1 = bHi0 + 16 * ROWB;
    const uint32_t bLo0 = sb + OFF_WLO + n0 * ROWB + boff, bLo1 = bLo0 + 16 * ROWB;

    // pointwise lane constants
    const int p = lane & 1;                       // 0: holds (i,j), 1: holds (f,o)
    const int prow = (lane >> 2) + (p ? 8 : 0);   // row within 16-row tile
    const int uofs = (lane >> 1) & 1;

    float c_state[8];
#pragma unroll
    for (int i = 0; i < 8; i++) c_state[i] = 0.0f;

    float* Gf = (float*)(smem + OFF_G);

    for (int t = 0; t < T_STEPS; ++t) {
        const uint32_t cbo = (t & 1) * ABYTES;
        const uint32_t nbo = ((t + 1) & 1) * ABYTES;

        // prefetch x_{t+1} early (LDG hides under GEMM)
        float4 xq;
        const bool xgo = (t + 1 < T_STEPS) && rowOK;
        if (xgo) xq = __ldg(xp + (size_t)(t + 1) * (F_IN / 4));

        // ---- GEMM: acc[mf][nfi][4]
        float acc[2][4][4];
#pragma unroll
        for (int m = 0; m < 2; m++)
#pragma unroll
            for (int n = 0; n < 4; n++)
#pragma unroll
                for (int e = 0; e < 4; e++) acc[m][n][e] = 0.0f;

#pragma unroll
        for (int kf = 0; kf < 6; kf++) {
            const int ko = kf * 32;
            uint32_t Ah[2][4], Al[2][4], Bh[8], Bl[8];
            ldsm4(Ah[0], aHi0 + cbo + ko);
            ldsm4(Ah[1], aHi1 + cbo + ko);
            ldsm4(Al[0], aLo0 + cbo + ko);
            ldsm4(Al[1], aLo1 + cbo + ko);
            ldsm4(Bh,     bHi0 + ko);
            ldsm4(Bh + 4, bHi1 + ko);
            ldsm4(Bl,     bLo0 + ko);
            ldsm4(Bl + 4, bLo1 + ko);
#pragma unroll
            for (int m = 0; m < 2; m++)
#pragma unroll
                for (int n = 0; n < 4; n++) mma16816(acc[m][n], Ah[m], Bh + 2 * n);
#pragma unroll
            for (int m = 0; m < 2; m++)
#pragma unroll
                for (int n = 0; n < 4; n++) mma16816(acc[m][n], Ah[m], Bl + 2 * n);
#pragma unroll
            for (int m = 0; m < 2; m++)
#pragma unroll
                for (int n = 0; n < 4; n++) mma16816(acc[m][n], Al[m], Bh + 2 * n);
        }

        // ---- pointwise: each lane recombines gates via 2 shfl per tile
        const bool last = (t == T_STEPS - 1);
#pragma unroll
        for (int m = 0; m < 2; m++) {
#pragma unroll
            for (int n = 0; n < 4; n++) {
                float* a = acc[m][n];
                float s0 = p ? a[0] : a[2];
                float s1 = p ? a[1] : a[3];
                float r0 = __shfl_xor_sync(0xFFFFFFFFu, s0, 1);
                float r1 = __shfl_xor_sync(0xFFFFFFFFu, s1, 1);
                float gi = p ? r0 : a[0];
                float gj = p ? r1 : a[1];
                float gf = p ? a[2] : r0;
                float go = p ? a[3] : r1;
                const int u   = wid * 8 + 2 * n + uofs;
                const int row = m * 16 + prow;
                const int ti  = m * 4 + n;
                float ig = sigmoid_f(gi);
                float jg = tanh_f(gj);
                float fg = sigmoid_f(gf);          // forget bias folded into W
                float og = sigmoid_f(go);
                float c2 = c_state[ti] * fg + ig * jg;
                c_state[ti] = c2;
                float h = tanh_f(c2) * og;
                if (u < H_DIM) {
                    uint32_t lo;
                    uint32_t hi = pack_hi_lo(h, lo);
                    const int ho = row * ROWB + (F_IN + u) * 2;
                    *(uint16_t*)(smem + OFF_AHI + nbo + ho) = (uint16_t)hi;
                    *(uint16_t*)(smem + OFF_ALO + nbo + ho) = (uint16_t)lo;
                    if (last) Gf[row * 64 + u] = h;
                }
            }
        }

        // ---- store x_{t+1} into next buffer
        if (xgo) {
            uint32_t l0, l1, l2, l3;
            uint32_t h0 = pack_hi_lo(xq.x, l0), h1 = pack_hi_lo(xq.y, l1);
            uint32_t h2 = pack_hi_lo(xq.z, l2), h3 = pack_hi_lo(xq.w, l3);
            *(uint2*)(smem + OFF_AHI + nbo + xoff) = make_uint2(h0 | (h1 << 16), h2 | (h3 << 16));
            *(uint2*)(smem + OFF_ALO + nbo + xoff) = make_uint2(l0 | (l1 << 16), l2 | (l3 << 16));
        }

        __syncthreads();   // next buffer fully written; all reads of it long done
    }

    // ---- final dense
    if (tid < ROWS && (row0 + tid) < Btotal) {
        float s = __ldg(dense_b);
        const float* hr = Gf + tid * 64;
#pragma unroll
        for (int u = 0; u < H_DIM; u++) s = fmaf(hr[u], __ldg(&dense_w[u]), s);
        out[row0 + tid] = s;
    }
}

extern "C" void kernel_launch(void* const* d_in, const int* in_sizes, int n_in,
                              void* d_out, int out_size)
{
    const float* x       = (const float*)d_in[0];
    const float* kernel  = (const float*)d_in[1];
    const float* bias    = (const float*)d_in[2];
    const float* dense_w = (const float*)d_in[3];
    const float* dense_b = (const float*)d_in[4];
    float* out = (float*)d_out;

    int Btotal = in_sizes[0] / (T_STEPS * F_IN);    // 4096
    int grid   = (Btotal + ROWS - 1) / ROWS;        // 128

    cudaFuncSetAttribute(lstm_mma_kernel,
                         cudaFuncAttributeMaxDynamicSharedMemorySize, SMEM_BYTES);

    lstm_mma_kernel<<<grid, THREADS, SMEM_BYTES>>>(
        x, kernel, bias, dense_w, dense_b, out, Btotal);
}

// round 6
// speedup vs baseline: 2.4782x; 1.0269x over previous
#include <cuda_runtime.h>
#include <cuda_bf16.h>
#include <cstdint>

// LSTM B=4096,T=512,F=32,H=60 via mma.sync.m16n8k16 bf16 (3-term hi/lo).
// 128 persistent CTAs x 32 rows. Per step: gates[32x240] = A[32x96]·W^T.
// A cols: 0..31 x_t, 32..91 h, 92 = 1.0 (bias incl. forget), 93..95 zero.
// N gate-interleaved: n = 4u+g; W padded to 256 rows. Warp w owns n in [32w,32w+32).
// R6: W fragments hoisted to registers (loaded once), A ldsm software-pipelined,
// GEMM(m0),GEMM(m1),PW(m0),PW(m1) order so MUFU overlaps tensor drain.

#define T_STEPS 512
#define F_IN    32
#define H_DIM   60
#define ROWS    32
#define THREADS 256

#define ASTR    104                  // bf16 per A/W row (208 B, conflict-free)
#define ROWB    208
#define ABYTES  (ROWS * ROWB)        // 6656
#define WROWS   256
#define WBYTES  (WROWS * ROWB)       // 53248

#define OFF_AHI 0                    // 2 bufs
#define OFF_ALO (2 * ABYTES)         // 13312 (2 bufs)
#define OFF_WHI (4 * ABYTES)         // 26624
#define OFF_WLO (OFF_WHI + WBYTES)   // 79872
#define OFF_G   (OFF_WLO + WBYTES)   // 133120 : 32 x 64 f32
#define SMEM_BYTES (OFF_G + ROWS * 64 * 4)   // 141312

static __device__ __forceinline__ uint32_t smem_u32(const void* p) {
    uint32_t a;
    asm("{ .reg .u64 t; cvta.to.shared.u64 t, %1; cvt.u32.u64 %0, t; }" : "=r"(a) : "l"(p));
    return a;
}
static __device__ __forceinline__ void ldsm4(uint32_t* r, uint32_t addr) {
    asm volatile("ldmatrix.sync.aligned.m8n8.x4.shared.b16 {%0,%1,%2,%3}, [%4];"
        : "=r"(r[0]), "=r"(r[1]), "=r"(r[2]), "=r"(r[3]) : "r"(addr));
}
static __device__ __forceinline__ void mma16816(float* d, const uint32_t* a, const uint32_t* b) {
    asm volatile("mma.sync.aligned.m16n8k16.row.col.f32.bf16.bf16.f32 "
        "{%0,%1,%2,%3}, {%4,%5,%6,%7}, {%8,%9}, {%0,%1,%2,%3};"
        : "+f"(d[0]), "+f"(d[1]), "+f"(d[2]), "+f"(d[3])
        : "r"(a[0]), "r"(a[1]), "r"(a[2]), "r"(a[3]), "r"(b[0]), "r"(b[1]));
}
static __device__ __forceinline__ float sigmoid_f(float x) {
    return __fdividef(1.0f, 1.0f + __expf(-x));
}
static __device__ __forceinline__ float tanh_f(float x) {
    float e = __expf(-2.0f * fabsf(x));
    float r = __fdividef(1.0f - e, 1.0f + e);
    return copysignf(r, x);
}
static __device__ __forceinline__ uint32_t pack_hi_lo(float v, uint32_t& lo16) {
    __nv_bfloat16 hb = __float2bfloat16_rn(v);
    __nv_bfloat16 lb = __float2bfloat16_rn(v - __bfloat162float(hb));
    lo16 = *(uint16_t*)&lb;
    return *(uint16_t*)&hb;
}

__global__ void __launch_bounds__(THREADS, 1)
lstm_mma_kernel(const float* __restrict__ x,
                const float* __restrict__ kernel,   // [92][240] cols g*60+u
                const float* __restrict__ bias,     // [240]
                const float* __restrict__ dense_w,  // [60]
                const float* __restrict__ dense_b,  // [1]
                float* __restrict__ out, int Btotal)
{
    extern __shared__ char smem[];
    const uint32_t sb = smem_u32(smem);
    const int tid = threadIdx.x, wid = tid >> 5, lane = tid & 31;
    const int row0 = blockIdx.x * ROWS;

    // ---- init: zero A region (both terms, both bufs)
    for (int i = tid; i < OFF_WHI / 4; i += THREADS) ((uint32_t*)smem)[i] = 0u;
    // W hi/lo, gate-interleaved, padded to 256 rows; bias(+forget) at k=92
    for (int idx = tid; idx < WROWS * ASTR; idx += THREADS) {
        int n = idx / ASTR, k = idx - n * ASTR;
        float v = 0.0f;
        if (n < 240) {
            int g = n & 3, u = n >> 2;
            if (k < 92)       v = kernel[k * 240 + g * 60 + u];
            else if (k == 92) v = bias[g * 60 + u] + (g == 2 ? 1.0f : 0.0f);
        }
        __nv_bfloat16 hb = __float2bfloat16_rn(v);
        *(__nv_bfloat16*)(smem + OFF_WHI + n * ROWB + k * 2) = hb;
        *(__nv_bfloat16*)(smem + OFF_WLO + n * ROWB + k * 2) =
            __float2bfloat16_rn(v - __bfloat162float(hb));
    }
    __syncthreads();

    // ones (bias) column k=92 in both A-hi buffers
    if (tid < ROWS) {
        __nv_bfloat16 one = __float2bfloat16_rn(1.0f);
        *(__nv_bfloat16*)(smem + OFF_AHI + tid * ROWB + 92 * 2) = one;
        *(__nv_bfloat16*)(smem + OFF_AHI + ABYTES + tid * ROWB + 92 * 2) = one;
    }

    // ---- x mapping: thread -> (row jr = tid/8, quad q = tid%8)
    const int jr = tid >> 3, q = tid & 7;
    const bool rowOK = (row0 + jr) < Btotal;
    const float4* xp = (const float4*)(x + (size_t)(row0 + jr) * (T_STEPS * F_IN)) + q;
    const int xoff = jr * ROWB + q * 8;

    // store x_0 into buf0
    if (rowOK) {
        float4 v = __ldg(xp);
        uint32_t l0, l1, l2, l3;
        uint32_t h0 = pack_hi_lo(v.x, l0), h1 = pack_hi_lo(v.y, l1);
        uint32_t h2 = pack_hi_lo(v.z, l2), h3 = pack_hi_lo(v.w, l3);
        *(uint2*)(smem + OFF_AHI + xoff) = make_uint2(h0 | (h1 << 16), h2 | (h3 << 16));
        *(uint2*)(smem + OFF_ALO + xoff) = make_uint2(l0 | (l1 << 16), l2 | (l3 << 16));
    }
    __syncthreads();

    // ---- per-lane ldmatrix offsets
    const int aoff = (lane & 15) * ROWB + (lane >> 4) * 16;                 // A frag
    const int boff = ((lane & 7) + ((lane & 16) ? 8 : 0)) * ROWB
                   + ((lane & 8) ? 16 : 0);                                 // B frag
    const int n0 = wid * 32;
    const uint32_t bHi0 = sb + OFF_WHI + n0 * ROWB + boff, bHi1 = bHi0 + 16 * ROWB;
    const uint32_t bLo0 = sb + OFF_WLO + n0 * ROWB + boff, bLo1 = bLo0 + 16 * ROWB;

    // ---- hoist W fragments into registers (invariant across t)
    uint32_t Bh[6][8], Bl[6][8];
#pragma unroll
    for (int kf = 0; kf < 6; kf++) {
        const int ko = kf * 32;
        ldsm4(&Bh[kf][0], bHi0 + ko);
        ldsm4(&Bh[kf][4], bHi1 + ko);
        ldsm4(&Bl[kf][0], bLo0 + ko);
        ldsm4(&Bl[kf][4], bLo1 + ko);
    }

    // pointwise lane constants
    const int p = lane & 1;                       // 0: holds (i,j), 1: holds (f,o)
    const int prow = (lane >> 2) + (p ? 8 : 0);   // row within 16-row tile
    const int uofs = (lane >> 1) & 1;

    float c_state[8];
#pragma unroll
    for (int i = 0; i < 8; i++) c_state[i] = 0.0f;

    float* Gf = (float*)(smem + OFF_G);

    for (int t = 0; t < T_STEPS; ++t) {
        const uint32_t cbo = (t & 1) * ABYTES;
        const uint32_t nbo = ((t + 1) & 1) * ABYTES;

        // prefetch x_{t+1} early (LDG hides under GEMM)
        float4 xq;
        const bool xgo = (t + 1 < T_STEPS) && rowOK;
        if (xgo) xq = __ldg(xp + (size_t)(t + 1) * (F_IN / 4));

        // ---- GEMM: both m tiles back-to-back (A ldsm software-pipelined)
        float acc[2][4][4];
#pragma unroll
        for (int m = 0; m < 2; m++)
#pragma unroll
            for (int n = 0; n < 4; n++)
#pragma unroll
                for (int e = 0; e < 4; e++) acc[m][n][e] = 0.0f;

#pragma unroll
        for (int m = 0; m < 2; m++) {
            const uint32_t aH = sb + OFF_AHI + cbo + aoff + m * 16 * ROWB;
            const uint32_t aL = sb + OFF_ALO + cbo + aoff + m * 16 * ROWB;
            uint32_t Ah[2][4], Al[2][4];
            ldsm4(Ah[0], aH);
            ldsm4(Al[0], aL);
#pragma unroll
            for (int kf = 0; kf < 6; kf++) {
                const int cur = kf & 1;
                if (kf < 5) {
                    ldsm4(Ah[cur ^ 1], aH + (kf + 1) * 32);
                    ldsm4(Al[cur ^ 1], aL + (kf + 1) * 32);
                }
#pragma unroll
                for (int n = 0; n < 4; n++) mma16816(acc[m][n], Ah[cur], &Bh[kf][2 * n]);
#pragma unroll
                for (int n = 0; n < 4; n++) mma16816(acc[m][n], Ah[cur], &Bl[kf][2 * n]);
#pragma unroll
                for (int n = 0; n < 4; n++) mma16816(acc[m][n], Al[cur], &Bh[kf][2 * n]);
            }
        }

        // ---- pointwise (m0 issues while m1 HMMA still drains in tensor pipe)
        const bool last = (t == T_STEPS - 1);
#pragma unroll
        for (int m = 0; m < 2; m++) {
#pragma unroll
            for (int n = 0; n < 4; n++) {
                float* a = acc[m][n];
                float s0 = p ? a[0] : a[2];
                float s1 = p ? a[1] : a[3];
                float r0 = __shfl_xor_sync(0xFFFFFFFFu, s0, 1);
                float r1 = __shfl_xor_sync(0xFFFFFFFFu, s1, 1);
                float gi = p ? r0 : a[0];
                float gj = p ? r1 : a[1];
                float gf = p ? a[2] : r0;
                float go = p ? a[3] : r1;
                const int u   = wid * 8 + 2 * n + uofs;
                const int row = m * 16 + prow;
                const int ti  = m * 4 + n;
                float ig = sigmoid_f(gi);
                float jg = tanh_f(gj);
                float fg = sigmoid_f(gf);          // forget bias folded into W
                float og = sigmoid_f(go);
                float c2 = c_state[ti] * fg + ig * jg;
                c_state[ti] = c2;
                float h = tanh_f(c2) * og;
                if (u < H_DIM) {
                    uint32_t lo;
                    uint32_t hi = pack_hi_lo(h, lo);
                    const int ho = row * ROWB + (F_IN + u) * 2;
                    *(uint16_t*)(smem + OFF_AHI + nbo + ho) = (uint16_t)hi;
                    *(uint16_t*)(smem + OFF_ALO + nbo + ho) = (uint16_t)lo;
                    if (last) Gf[row * 64 + u] = h;
                }
            }
        }

        // ---- store x_{t+1} into next buffer
        if (xgo) {
            uint32_t l0, l1, l2, l3;
            uint32_t h0 = pack_hi_lo(xq.x, l0), h1 = pack_hi_lo(xq.y, l1);
            uint32_t h2 = pack_hi_lo(xq.z, l2), h3 = pack_hi_lo(xq.w, l3);
            *(uint2*)(smem + OFF_AHI + nbo + xoff) = make_uint2(h0 | (h1 << 16), h2 | (h3 << 16));
            *(uint2*)(smem + OFF_ALO + nbo + xoff) = make_uint2(l0 | (l1 << 16), l2 | (l3 << 16));
        }

        __syncthreads();   // next buffer fully written; all reads of it long done
    }

    // ---- final dense
    if (tid < ROWS && (row0 + tid) < Btotal) {
        float s = __ldg(dense_b);
        const float* hr = Gf + tid * 64;
#pragma unroll
        for (int u = 0; u < H_DIM; u++) s = fmaf(hr[u], __ldg(&dense_w[u]), s);
        out[row0 + tid] = s;
    }
}

extern "C" void kernel_launch(void* const* d_in, const int* in_sizes, int n_in,
                              void* d_out, int out_size)
{
    const float* x       = (const float*)d_in[0];
    const float* kernel  = (const float*)d_in[1];
    const float* bias    = (const float*)d_in[2];
    const float* dense_w = (const float*)d_in[3];
    const float* dense_b = (const float*)d_in[4];
    float* out = (float*)d_out;

    int Btotal = in_sizes[0] / (T_STEPS * F_IN);    // 4096
    int grid   = (Btotal + ROWS - 1) / ROWS;        // 128

    cudaFuncSetAttribute(lstm_mma_kernel,
                         cudaFuncAttributeMaxDynamicSharedMemorySize, SMEM_BYTES);

    lstm_mma_kernel<<<grid, THREADS, SMEM_BYTES>>>(
        x, kernel, bias, dense_w, dense_b, out, Btotal);
}

// round 7
// speedup vs baseline: 2.8402x; 1.1461x over previous
#include <cuda_runtime.h>
#include <cuda_bf16.h>
#include <cstdint>

// LSTM B=4096,T=512,F=32,H=60 via mma.sync.m16n8k16 bf16 (3-term hi/lo).
// R7: 256 CTAs x 16 rows, 2 CTAs/SM co-resident (anti-phase overlap).
// Per step: gates[16x240] = A[16x96]·W^T. W exactly 240 rows in SMEM.
// A cols: 0..31 x_t, 32..91 h, 92 = 1.0 (bias incl. forget), 93..95 zero.
// N gate-interleaved: n = 4u+g. Warp w owns n in [32w, 32w+32); warp 7 only 16.

#define T_STEPS 512
#define F_IN    32
#define H_DIM   60
#define ROWS    16
#define THREADS 256

#define ASTR    104                   // bf16 per row (208 B, ldsm conflict-free)
#define ROWB    208
#define ABUF    (ROWS * ROWB)         // 3328 per term per buffer
#define WROWS   240
#define WBYTES  (WROWS * ROWB)        // 49920

#define OFF_WHI 0
#define OFF_WLO WBYTES                // 49920
#define OFF_AHI (2 * WBYTES)         // 99840 (2 bufs)
#define OFF_ALO (OFF_AHI + 2 * ABUF) // 106496 (2 bufs)
#define SMEM_BYTES (OFF_ALO + 2 * ABUF)   // 113152
// G overlay (post-loop only): 16 x 64 f32 at offset 0 (dead W region)

static __device__ __forceinline__ uint32_t smem_u32(const void* p) {
    uint32_t a;
    asm("{ .reg .u64 t; cvta.to.shared.u64 t, %1; cvt.u32.u64 %0, t; }" : "=r"(a) : "l"(p));
    return a;
}
static __device__ __forceinline__ void ldsm4(uint32_t* r, uint32_t addr) {
    asm volatile("ldmatrix.sync.aligned.m8n8.x4.shared.b16 {%0,%1,%2,%3}, [%4];"
        : "=r"(r[0]), "=r"(r[1]), "=r"(r[2]), "=r"(r[3]) : "r"(addr));
}
static __device__ __forceinline__ void mma16816(float* d, const uint32_t* a, const uint32_t* b) {
    asm volatile("mma.sync.aligned.m16n8k16.row.col.f32.bf16.bf16.f32 "
        "{%0,%1,%2,%3}, {%4,%5,%6,%7}, {%8,%9}, {%0,%1,%2,%3};"
        : "+f"(d[0]), "+f"(d[1]), "+f"(d[2]), "+f"(d[3])
        : "r"(a[0]), "r"(a[1]), "r"(a[2]), "r"(a[3]), "r"(b[0]), "r"(b[1]));
}
static __device__ __forceinline__ float sigmoid_f(float x) {
    return __fdividef(1.0f, 1.0f + __expf(-x));
}
static __device__ __forceinline__ float tanh_f(float x) {
    float e = __expf(-2.0f * fabsf(x));
    float r = __fdividef(1.0f - e, 1.0f + e);
    return copysignf(r, x);
}
static __device__ __forceinline__ uint32_t pack_hi_lo(float v, uint32_t& lo16) {
    __nv_bfloat16 hb = __float2bfloat16_rn(v);
    __nv_bfloat16 lb = __float2bfloat16_rn(v - __bfloat162float(hb));
    lo16 = *(uint16_t*)&lb;
    return *(uint16_t*)&hb;
}

__global__ void __launch_bounds__(THREADS, 2)
lstm_mma_kernel(const float* __restrict__ x,
                const float* __restrict__ kernel,   // [92][240] cols g*60+u
                const float* __restrict__ bias,     // [240]
                const float* __restrict__ dense_w,  // [60]
                const float* __restrict__ dense_b,  // [1]
                float* __restrict__ out, int Btotal)
{
    extern __shared__ char smem[];
    const uint32_t sb = smem_u32(smem);
    const int tid = threadIdx.x, wid = tid >> 5, lane = tid & 31;
    const int row0 = blockIdx.x * ROWS;

    // ---- init: zero A region (both terms, both bufs)
    for (int i = tid; i < 4 * ABUF / 4; i += THREADS)
        ((uint32_t*)(smem + OFF_AHI))[i] = 0u;
    // W hi/lo, gate-interleaved, 240 rows; bias(+forget) folded at k=92
    for (int idx = tid; idx < WROWS * ASTR; idx += THREADS) {
        int n = idx / ASTR, k = idx - n * ASTR;
        int g = n & 3, u = n >> 2;
        float v = 0.0f;
        if (k < 92)       v = kernel[k * 240 + g * 60 + u];
        else if (k == 92) v = bias[g * 60 + u] + (g == 2 ? 1.0f : 0.0f);
        __nv_bfloat16 hb = __float2bfloat16_rn(v);
        *(__nv_bfloat16*)(smem + OFF_WHI + n * ROWB + k * 2) = hb;
        *(__nv_bfloat16*)(smem + OFF_WLO + n * ROWB + k * 2) =
            __float2bfloat16_rn(v - __bfloat162float(hb));
    }
    __syncthreads();

    // ones (bias) column k=92 in both A-hi buffers
    if (tid < ROWS) {
        __nv_bfloat16 one = __float2bfloat16_rn(1.0f);
        *(__nv_bfloat16*)(smem + OFF_AHI + tid * ROWB + 92 * 2) = one;
        *(__nv_bfloat16*)(smem + OFF_AHI + ABUF + tid * ROWB + 92 * 2) = one;
    }

    // ---- x mapping: thread -> (row jr = tid/16, col pair q = tid%16)
    const int jr = tid >> 4, q = tid & 15;
    const bool rowOK = (row0 + jr) < Btotal;
    const float2* xp = (const float2*)(x + (size_t)(row0 + jr) * (T_STEPS * F_IN)) + q;
    const int xoff = jr * ROWB + q * 4;

    // store x_0 into buf0
    if (rowOK) {
        float2 v = __ldg(xp);
        uint32_t l0, l1;
        uint32_t h0 = pack_hi_lo(v.x, l0), h1 = pack_hi_lo(v.y, l1);
        *(uint32_t*)(smem + OFF_AHI + xoff) = h0 | (h1 << 16);
        *(uint32_t*)(smem + OFF_ALO + xoff) = l0 | (l1 << 16);
    }
    __syncthreads();

    // ---- per-lane ldmatrix offsets
    const int aoff = (lane & 15) * ROWB + (lane >> 4) * 16;       // A frag (16x16)
    const int boff = ((lane & 7) + ((lane & 16) ? 8 : 0)) * ROWB
                   + ((lane & 8) ? 16 : 0);                       // B frag (16 rows)
    const int n0 = wid * 32;
    const bool have2 = (n0 + 16) < WROWS;                         // warp 7: false
    const uint32_t bHi0 = sb + OFF_WHI + n0 * ROWB + boff;
    const uint32_t bLo0 = sb + OFF_WLO + n0 * ROWB + boff;
    const uint32_t bHi1 = bHi0 + (have2 ? 16 * ROWB : 0);
    const uint32_t bLo1 = bLo0 + (have2 ? 16 * ROWB : 0);

    // pointwise lane constants
    const int p = lane & 1;                       // 0: keeps row g, 1: row g+8
    const int prow = (lane >> 2) + (p ? 8 : 0);
    const int uofs = (lane >> 1) & 1;

    float c_state[4], hreg[4];
#pragma unroll
    for (int i = 0; i < 4; i++) { c_state[i] = 0.0f; hreg[i] = 0.0f; }

    for (int t = 0; t < T_STEPS; ++t) {
        const uint32_t cbo = (t & 1) * ABUF;
        const uint32_t nbo = ((t + 1) & 1) * ABUF;

        // prefetch x_{t+1} early (LDG hides under GEMM)
        float2 xq;
        const bool xgo = (t + 1 < T_STEPS) && rowOK;
        if (xgo) xq = __ldg(xp + (size_t)(t + 1) * (F_IN / 2));

        // ---- GEMM: acc[4 n-frags][4]
        float acc[4][4];
#pragma unroll
        for (int n = 0; n < 4; n++)
#pragma unroll
            for (int e = 0; e < 4; e++) acc[n][e] = 0.0f;

        const uint32_t aH = sb + OFF_AHI + cbo + aoff;
        const uint32_t aL = sb + OFF_ALO + cbo + aoff;
#pragma unroll
        for (int kf = 0; kf < 6; kf++) {
            const int ko = kf * 32;
            uint32_t Ah[4], Al[4], Bh[8], Bl[8];
            ldsm4(Ah, aH + ko);
            ldsm4(Al, aL + ko);
            ldsm4(Bh, bHi0 + ko);
            ldsm4(Bl, bLo0 + ko);
            if (have2) {
                ldsm4(Bh + 4, bHi1 + ko);
                ldsm4(Bl + 4, bLo1 + ko);
            }
            mma16816(acc[0], Ah, Bh + 0);
            mma16816(acc[1], Ah, Bh + 2);
            mma16816(acc[0], Ah, Bl + 0);
            mma16816(acc[1], Ah, Bl + 2);
            mma16816(acc[0], Al, Bh + 0);
            mma16816(acc[1], Al, Bh + 2);
            if (have2) {
                mma16816(acc[2], Ah, Bh + 4);
                mma16816(acc[3], Ah, Bh + 6);
                mma16816(acc[2], Ah, Bl + 4);
                mma16816(acc[3], Ah, Bl + 6);
                mma16816(acc[2], Al, Bh + 4);
                mma16816(acc[3], Al, Bh + 6);
            }
        }

        // ---- pointwise: lane pair shfl recombines (i,j)/(f,o)
        const bool last = (t == T_STEPS - 1);
#pragma unroll
        for (int f = 0; f < 4; f++) {
            if (f >= 2 && !have2) break;
            float* a = acc[f];
            float s0 = p ? a[0] : a[2];
            float s1 = p ? a[1] : a[3];
            float r0 = __shfl_xor_sync(0xFFFFFFFFu, s0, 1);
            float r1 = __shfl_xor_sync(0xFFFFFFFFu, s1, 1);
            float gi = p ? r0 : a[0];
            float gj = p ? r1 : a[1];
            float gf = p ? a[2] : r0;
            float go = p ? a[3] : r1;
            const int u = wid * 8 + 2 * f + uofs;
            float ig = sigmoid_f(gi);
            float jg = tanh_f(gj);
            float fg = sigmoid_f(gf);          // forget bias folded into W
            float og = sigmoid_f(go);
            float c2 = c_state[f] * fg + ig * jg;
            c_state[f] = c2;
            float h = tanh_f(c2) * og;
            if (u < H_DIM) {
                uint32_t lo;
                uint32_t hi = pack_hi_lo(h, lo);
                const int ho = prow * ROWB + (F_IN + u) * 2;
                *(uint16_t*)(smem + OFF_AHI + nbo + ho) = (uint16_t)hi;
                *(uint16_t*)(smem + OFF_ALO + nbo + ho) = (uint16_t)lo;
                if (last) hreg[f] = h;
            }
        }

        // ---- store x_{t+1} into next buffer
        if (xgo) {
            uint32_t l0, l1;
            uint32_t h0 = pack_hi_lo(xq.x, l0), h1 = pack_hi_lo(xq.y, l1);
            *(uint32_t*)(smem + OFF_AHI + nbo + xoff) = h0 | (h1 << 16);
            *(uint32_t*)(smem + OFF_ALO + nbo + xoff) = l0 | (l1 << 16);
        }

        __syncthreads();
    }

    // ---- stage final h (fp32) into dead W region, then dense
    float* Gf = (float*)smem;      // 16 x 64
#pragma unroll
    for (int f = 0; f < 4; f++) {
        const int u = wid * 8 + 2 * f + uofs;
        if (u < H_DIM) Gf[prow * 64 + u] = hreg[f];
    }
    __syncthreads();

    if (tid < ROWS && (row0 + tid) < Btotal) {
        float s = __ldg(dense_b);
        const float* hr = Gf + tid * 64;
#pragma unroll
        for (int u = 0; u < H_DIM; u++) s = fmaf(hr[u], __ldg(&dense_w[u]), s);
        out[row0 + tid] = s;
    }
}

extern "C" void kernel_launch(void* const* d_in, const int* in_sizes, int n_in,
                              void* d_out, int out_size)
{
    const float* x       = (const float*)d_in[0];
    const float* kernel  = (const float*)d_in[1];
    const float* bias    = (const float*)d_in[2];
    const float* dense_w = (const float*)d_in[3];
    const float* dense_b = (const float*)d_in[4];
    float* out = (float*)d_out;

    int Btotal = in_sizes[0] / (T_STEPS * F_IN);    // 4096
    int grid   = (Btotal + ROWS - 1) / ROWS;        // 256

    cudaFuncSetAttribute(lstm_mma_kernel,
                         cudaFuncAttributeMaxDynamicSharedMemorySize, SMEM_BYTES);

    lstm_mma_kernel<<<grid, THREADS, SMEM_BYTES>>>(
        x, kernel, bias, dense_w, dense_b, out, Btotal);
}

// round 8
// speedup vs baseline: 2.8631x; 1.0080x over previous
#include <cuda_runtime.h>
#include <cuda_bf16.h>
#include <cstdint>

// LSTM B=4096,T=512,F=32,H=60 via mma.sync.m16n8k16 bf16 (3-term hi/lo).
// R8: 256 CTAs x 16 rows, 2/SM. Shfl-free gate layout: warp w, frag 2fp   -> (i,j)
// and frag 2fp+1 -> (f,o) of cells u = 8w+4fp+c (c = lane%4). Bh hoisted to regs.
// A cols: 0..31 x_t, 32..91 h, 92 = 1.0 (bias incl. forget), 93..95 zero.

#define T_STEPS 512
#define F_IN    32
#define H_DIM   60
#define ROWS    16
#define THREADS 256

#define ASTR    104                   // bf16 per row (208 B, ldsm conflict-free)
#define ROWB    208
#define ABUF    (ROWS * ROWB)         // 3328 per term per buffer
#define WROWS   240
#define WBYTES  (WROWS * ROWB)        // 49920

#define OFF_WHI 0
#define OFF_WLO WBYTES                // 49920
#define OFF_AHI (2 * WBYTES)         // 99840 (2 bufs)
#define OFF_ALO (OFF_AHI + 2 * ABUF) // 106496 (2 bufs)
#define SMEM_BYTES (OFF_ALO + 2 * ABUF)   // 113152

static __device__ __forceinline__ uint32_t smem_u32(const void* p) {
    uint32_t a;
    asm("{ .reg .u64 t; cvta.to.shared.u64 t, %1; cvt.u32.u64 %0, t; }" : "=r"(a) : "l"(p));
    return a;
}
static __device__ __forceinline__ void ldsm4(uint32_t* r, uint32_t addr) {
    asm volatile("ldmatrix.sync.aligned.m8n8.x4.shared.b16 {%0,%1,%2,%3}, [%4];"
        : "=r"(r[0]), "=r"(r[1]), "=r"(r[2]), "=r"(r[3]) : "r"(addr));
}
static __device__ __forceinline__ void mma16816(float* d, const uint32_t* a, const uint32_t* b) {
    asm volatile("mma.sync.aligned.m16n8k16.row.col.f32.bf16.bf16.f32 "
        "{%0,%1,%2,%3}, {%4,%5,%6,%7}, {%8,%9}, {%0,%1,%2,%3};"
        : "+f"(d[0]), "+f"(d[1]), "+f"(d[2]), "+f"(d[3])
        : "r"(a[0]), "r"(a[1]), "r"(a[2]), "r"(a[3]), "r"(b[0]), "r"(b[1]));
}
static __device__ __forceinline__ float sigmoid_f(float x) {
    return __fdividef(1.0f, 1.0f + __expf(-x));
}
static __device__ __forceinline__ float tanh_f(float x) {
    float e = __expf(-2.0f * fabsf(x));
    float r = __fdividef(1.0f - e, 1.0f + e);
    return copysignf(r, x);
}
static __device__ __forceinline__ uint32_t pack_hi_lo(float v, uint32_t& lo16) {
    __nv_bfloat16 hb = __float2bfloat16_rn(v);
    __nv_bfloat16 lb = __float2bfloat16_rn(v - __bfloat162float(hb));
    lo16 = *(uint16_t*)&lb;
    return *(uint16_t*)&hb;
}

__global__ void __launch_bounds__(THREADS, 2)
lstm_mma_kernel(const float* __restrict__ x,
                const float* __restrict__ kernel,   // [92][240] cols g*60+u
                const float* __restrict__ bias,     // [240]
                const float* __restrict__ dense_w,  // [60]
                const float* __restrict__ dense_b,  // [1]
                float* __restrict__ out, int Btotal)
{
    extern __shared__ char smem[];
    const uint32_t sb = smem_u32(smem);
    const int tid = threadIdx.x, wid = tid >> 5, lane = tid & 31;
    const int row0 = blockIdx.x * ROWS;

    // ---- init: zero A region (both terms, both bufs)
    for (int i = tid; i < 4 * ABUF / 4; i += THREADS)
        ((uint32_t*)(smem + OFF_AHI))[i] = 0u;
    // W hi/lo with shfl-free n-permutation; bias(+forget) folded at k=92.
    // n -> (gate g, cell u): w=n/32, r=n%32, F=r/8, fp=F/2, gp=F&1, j=r%8,
    // c=j/2, g1=j&1, u=8w+4fp+c, g=2*gp+g1  (gate order i,j,f,o)
    for (int idx = tid; idx < WROWS * ASTR; idx += THREADS) {
        int n = idx / ASTR, k = idx - n * ASTR;
        int w = n >> 5, r = n & 31, F = r >> 3, j = r & 7;
        int fp = F >> 1, gp = F & 1, c = j >> 1, g1 = j & 1;
        int u = 8 * w + 4 * fp + c;
        int g = 2 * gp + g1;
        float v = 0.0f;
        if (u < H_DIM) {
            if (k < 92)       v = kernel[k * 240 + g * 60 + u];
            else if (k == 92) v = bias[g * 60 + u] + (g == 2 ? 1.0f : 0.0f);
        }
        __nv_bfloat16 hb = __float2bfloat16_rn(v);
        *(__nv_bfloat16*)(smem + OFF_WHI + n * ROWB + k * 2) = hb;
        *(__nv_bfloat16*)(smem + OFF_WLO + n * ROWB + k * 2) =
            __float2bfloat16_rn(v - __bfloat162float(hb));
    }
    __syncthreads();

    // ones (bias) column k=92 in both A-hi buffers
    if (tid < ROWS) {
        __nv_bfloat16 one = __float2bfloat16_rn(1.0f);
        *(__nv_bfloat16*)(smem + OFF_AHI + tid * ROWB + 92 * 2) = one;
        *(__nv_bfloat16*)(smem + OFF_AHI + ABUF + tid * ROWB + 92 * 2) = one;
    }

    // ---- x mapping: thread -> (row jr = tid/16, col pair q = tid%16)
    const int jr = tid >> 4, q = tid & 15;
    const bool rowOK = (row0 + jr) < Btotal;
    const float2* xp = (const float2*)(x + (size_t)(row0 + jr) * (T_STEPS * F_IN)) + q;
    const int xoff = jr * ROWB + q * 4;

    // store x_0 into buf0
    if (rowOK) {
        float2 v = __ldg(xp);
        uint32_t l0, l1;
        uint32_t h0 = pack_hi_lo(v.x, l0), h1 = pack_hi_lo(v.y, l1);
        *(uint32_t*)(smem + OFF_AHI + xoff) = h0 | (h1 << 16);
        *(uint32_t*)(smem + OFF_ALO + xoff) = l0 | (l1 << 16);
    }
    __syncthreads();

    // ---- per-lane ldmatrix offsets
    const int aoff = (lane & 15) * ROWB + (lane >> 4) * 16;       // A frag (16x16)
    const int boff = ((lane & 7) + ((lane & 16) ? 8 : 0)) * ROWB
                   + ((lane & 8) ? 16 : 0);                       // B frag (16 rows)
    const int n0 = wid * 32;
    const bool have2 = (n0 + 16) < WROWS;                         // warp 7: false
    const uint32_t bHi0 = sb + OFF_WHI + n0 * ROWB + boff;
    const uint32_t bLo0 = sb + OFF_WLO + n0 * ROWB + boff;
    const uint32_t bHi1 = bHi0 + (have2 ? 16 * ROWB : 0);
    const uint32_t bLo1 = bLo0 + (have2 ? 16 * ROWB : 0);

    // ---- hoist Bh fragments to registers (invariant across t)
    uint32_t Bh[6][8];
#pragma unroll
    for (int kf = 0; kf < 6; kf++) {
        ldsm4(&Bh[kf][0], bHi0 + kf * 32);
        if (have2) ldsm4(&Bh[kf][4], bHi1 + kf * 32);
    }

    // pointwise lane constants (shfl-free): cell u = 8w + 4fp + (lane%4),
    // rows lane/4 and lane/4 + 8
    const int cc = lane & 3;
    const int prow0 = lane >> 2;

    float c_state[4], hreg[4];
#pragma unroll
    for (int i = 0; i < 4; i++) { c_state[i] = 0.0f; hreg[i] = 0.0f; }

    for (int t = 0; t < T_STEPS; ++t) {
        const uint32_t cbo = (t & 1) * ABUF;
        const uint32_t nbo = ((t + 1) & 1) * ABUF;

        // prefetch x_{t+1} early (LDG hides under GEMM)
        float2 xq;
        const bool xgo = (t + 1 < T_STEPS) && rowOK;
        if (xgo) xq = __ldg(xp + (size_t)(t + 1) * (F_IN / 2));

        // ---- GEMM: acc[frag F][4]
        float acc[4][4];
#pragma unroll
        for (int n = 0; n < 4; n++)
#pragma unroll
            for (int e = 0; e < 4; e++) acc[n][e] = 0.0f;

        const uint32_t aH = sb + OFF_AHI + cbo + aoff;
        const uint32_t aL = sb + OFF_ALO + cbo + aoff;
#pragma unroll
        for (int kf = 0; kf < 6; kf++) {
            const int ko = kf * 32;
            uint32_t Ah[4], Al[4], Bl[8];
            ldsm4(Ah, aH + ko);
            ldsm4(Al, aL + ko);
            ldsm4(Bl, bLo0 + ko);
            if (have2) ldsm4(Bl + 4, bLo1 + ko);
            mma16816(acc[0], Ah, &Bh[kf][0]);
            mma16816(acc[1], Ah, &Bh[kf][2]);
            mma16816(acc[0], Ah, Bl + 0);
            mma16816(acc[1], Ah, Bl + 2);
            mma16816(acc[0], Al, &Bh[kf][0]);
            mma16816(acc[1], Al, &Bh[kf][2]);
            if (have2) {
                mma16816(acc[2], Ah, &Bh[kf][4]);
                mma16816(acc[3], Ah, &Bh[kf][6]);
                mma16816(acc[2], Ah, Bl + 4);
                mma16816(acc[3], Ah, Bl + 6);
                mma16816(acc[2], Al, &Bh[kf][4]);
                mma16816(acc[3], Al, &Bh[kf][6]);
            }
        }

        // ---- pointwise, shfl-free: frags (2fp, 2fp+1) = (i,j), (f,o) of cell u
        const bool last = (t == T_STEPS - 1);
#pragma unroll
        for (int fp = 0; fp < 2; fp++) {
            if (fp == 1 && !have2) break;
            const float* aij = acc[2 * fp];
            const float* afo = acc[2 * fp + 1];
            const int u = 8 * wid + 4 * fp + cc;
#pragma unroll
            for (int rh = 0; rh < 2; rh++) {
                float gi = aij[2 * rh], gj = aij[2 * rh + 1];
                float gf = afo[2 * rh], go = afo[2 * rh + 1];
                const int si = 2 * fp + rh;
                float ig = sigmoid_f(gi);
                float jg = tanh_f(gj);
                float fg = sigmoid_f(gf);          // forget bias folded into W
                float og = sigmoid_f(go);
                float c2 = c_state[si] * fg + ig * jg;
                c_state[si] = c2;
                float h = tanh_f(c2) * og;
                uint32_t lo;
                uint32_t hi = pack_hi_lo(h, lo);
                const int ho = (prow0 + 8 * rh) * ROWB + (F_IN + u) * 2;
                *(uint16_t*)(smem + OFF_AHI + nbo + ho) = (uint16_t)hi;
                *(uint16_t*)(smem + OFF_ALO + nbo + ho) = (uint16_t)lo;
                if (last) hreg[si] = h;
            }
        }

        // ---- store x_{t+1} into next buffer
        if (xgo) {
            uint32_t l0, l1;
            uint32_t h0 = pack_hi_lo(xq.x, l0), h1 = pack_hi_lo(xq.y, l1);
            *(uint32_t*)(smem + OFF_AHI + nbo + xoff) = h0 | (h1 << 16);
            *(uint32_t*)(smem + OFF_ALO + nbo + xoff) = l0 | (l1 << 16);
        }

        __syncthreads();
    }

    // ---- stage final h (fp32) into dead W region, then dense
    float* Gf = (float*)smem;      // 16 x 64
#pragma unroll
    for (int fp = 0; fp < 2; fp++) {
        if (fp == 1 && !have2) break;
        const int u = 8 * wid + 4 * fp + cc;
#pragma unroll
        for (int rh = 0; rh < 2; rh++)
            Gf[(prow0 + 8 * rh) * 64 + u] = hreg[2 * fp + rh];
    }
    __syncthreads();

    if (tid < ROWS && (row0 + tid) < Btotal) {
        float s = __ldg(dense_b);
        const float* hr = Gf + tid * 64;
#pragma unroll
        for (int u = 0; u < H_DIM; u++) s = fmaf(hr[u], __ldg(&dense_w[u]), s);
        out[row0 + tid] = s;
    }
}

extern "C" void kernel_launch(void* const* d_in, const int* in_sizes, int n_in,
                              void* d_out, int out_size)
{
    const float* x       = (const float*)d_in[0];
    const float* kernel  = (const float*)d_in[1];
    const float* bias    = (const float*)d_in[2];
    const float* dense_w = (const float*)d_in[3];
    const float* dense_b = (const float*)d_in[4];
    float* out = (float*)d_out;

    int Btotal = in_sizes[0] / (T_STEPS * F_IN);    // 4096
    int grid   = (Btotal + ROWS - 1) / ROWS;        // 256

    cudaFuncSetAttribute(lstm_mma_kernel,
                         cudaFuncAttributeMaxDynamicSharedMemorySize, SMEM_BYTES);

    lstm_mma_kernel<<<grid, THREADS, SMEM_BYTES>>>(
        x, kernel, bias, dense_w, dense_b, out, Btotal);
}